// round 1
// baseline (speedup 1.0000x reference)
#include <cuda_runtime.h>

// ---------------------------------------------------------------------------
// MMD loss, restructured:
//   loss = (1/ns^2) * sum_{i,j} s_i s_j K_ij,  s_i = +1 (source) / -1 (target)
//   K_ij = sum_{k=0..4} exp(-l2_ij / bw_k),  l2_ij = sq_i + sq_j - 2 x_i.x_j
//   bandwidth from sum(l2) = 2n*sum(sq) - 2*||colsum||^2   (O(nD), no gram)
//   Symmetry K_ij = K_ji: only tiles tj >= ti, off-diagonal weighted x2.
// ---------------------------------------------------------------------------

#define NS    4096
#define DDIM  256
#define NTOT  8192
#define BM    128           // pair tile (BM x BM)
#define BK    16            // k-chunk
#define NTILES (NTOT / BM)  // 64
#define SSTR  (BM + 4)      // smem row stride in floats (132; 132*4 % 16 == 0)

__device__ float  g_sq[NTOT];
__device__ float  g_colsum[DDIM];
__device__ double g_acc;
__device__ float  g_c[5];   // log2(e) / bw_k

__device__ __forceinline__ const float* row_ptr(const float* __restrict__ s,
                                                const float* __restrict__ t,
                                                int row) {
    return (row < NS) ? (s + (size_t)row * DDIM) : (t + (size_t)(row - NS) * DDIM);
}

__device__ __forceinline__ float ex2(float x) {
    float r;
    asm("ex2.approx.ftz.f32 %0, %1;" : "=f"(r) : "f"(x));
    return r;
}

// ---------------------------------------------------------------------------
__global__ void init_kernel() {
    int t = threadIdx.x;
    if (t < DDIM) g_colsum[t] = 0.0f;
    if (t == 0)   g_acc = 0.0;
}

// 256 blocks x 256 threads; block b handles rows [b*32, b*32+32).
// thread t <-> column t. Produces g_sq[row] and g_colsum[col].
__global__ void prep_kernel(const float* __restrict__ src,
                            const float* __restrict__ tgt) {
    const int t = threadIdx.x;
    const int b = blockIdx.x;
    const int RPB = NTOT / 256;  // 32
    __shared__ float red[256];
    float colacc = 0.0f;

    for (int rr = 0; rr < RPB; rr++) {
        int row = b * RPB + rr;
        float x = row_ptr(src, tgt, row)[t];
        colacc += x;
        red[t] = x * x;
        __syncthreads();
        #pragma unroll
        for (int s = 128; s > 0; s >>= 1) {
            if (t < s) red[t] += red[t + s];
            __syncthreads();
        }
        if (t == 0) g_sq[row] = red[0];
        __syncthreads();
    }
    atomicAdd(&g_colsum[t], colacc);
}

// 1 block x 256 threads: bandwidth and exp2 coefficients.
__global__ void finalize_kernel() {
    const int t = threadIdx.x;
    __shared__ double red[256];

    double s = 0.0;
    for (int i = t; i < NTOT; i += 256) s += (double)g_sq[i];
    red[t] = s;
    __syncthreads();
    #pragma unroll
    for (int st = 128; st > 0; st >>= 1) {
        if (t < st) red[t] += red[t + st];
        __syncthreads();
    }
    double S = red[0];       // sum of sq  (all threads read before overwrite)
    __syncthreads();

    double c = (double)g_colsum[t];
    red[t] = c * c;
    __syncthreads();
    #pragma unroll
    for (int st = 128; st > 0; st >>= 1) {
        if (t < st) red[t] += red[t + st];
        __syncthreads();
    }

    if (t == 0) {
        double V      = red[0];                          // ||colsum||^2
        double n      = (double)NTOT;
        double sum_l2 = 2.0 * n * S - 2.0 * V;
        double bw     = sum_l2 / (n * n - n);
        bw /= 4.0;                                       // KERNEL_MUL^(KERNEL_NUM//2)
        const double LOG2E = 1.4426950408889634;
        #pragma unroll
        for (int k = 0; k < 5; k++)
            g_c[k] = (float)(LOG2E / (bw * (double)(1 << k)));
    }
}

// ---------------------------------------------------------------------------
// Main fused kernel: 128x128 pair tile per block, 256 threads, 8x8 micro-tile.
__global__ void __launch_bounds__(256) mmd_kernel(const float* __restrict__ src,
                                                  const float* __restrict__ tgt) {
    const int ti = blockIdx.y;
    const int tj = blockIdx.x;
    if (tj < ti) return;   // symmetry: upper triangle only

    __shared__ float As[BK][SSTR];
    __shared__ float Bs[BK][SSTR];

    const int tid = threadIdx.x;
    const int tx  = tid & 15;   // 16 cols of threads
    const int ty  = tid >> 4;   // 16 rows of threads

    const int i0 = ti * BM;
    const int j0 = tj * BM;

    float acc[8][8];
    #pragma unroll
    for (int a = 0; a < 8; a++)
        #pragma unroll
        for (int b = 0; b < 8; b++) acc[a][b] = 0.0f;

    // per-thread load coordinates: 512 float4 per tile chunk, 2 per thread
    const int r0 = tid >> 2;        // 0..63
    const int c0 = tid & 3;         // 0..3  (float4 column within 16-float row)

    for (int kk = 0; kk < DDIM; kk += BK) {
        #pragma unroll
        for (int l = 0; l < 2; l++) {
            int r = r0 + l * 64;
            float4 va = *(const float4*)(row_ptr(src, tgt, i0 + r) + kk + c0 * 4);
            float4 vb = *(const float4*)(row_ptr(src, tgt, j0 + r) + kk + c0 * 4);
            int kb = c0 * 4;
            As[kb + 0][r] = va.x; As[kb + 1][r] = va.y;
            As[kb + 2][r] = va.z; As[kb + 3][r] = va.w;
            Bs[kb + 0][r] = vb.x; Bs[kb + 1][r] = vb.y;
            Bs[kb + 2][r] = vb.z; Bs[kb + 3][r] = vb.w;
        }
        __syncthreads();

        #pragma unroll
        for (int k = 0; k < BK; k++) {
            float4 a0 = *(const float4*)&As[k][ty * 8];
            float4 a1 = *(const float4*)&As[k][ty * 8 + 4];
            float4 b0 = *(const float4*)&Bs[k][tx * 8];
            float4 b1 = *(const float4*)&Bs[k][tx * 8 + 4];
            float av[8] = {a0.x, a0.y, a0.z, a0.w, a1.x, a1.y, a1.z, a1.w};
            float bv[8] = {b0.x, b0.y, b0.z, b0.w, b1.x, b1.y, b1.z, b1.w};
            #pragma unroll
            for (int ii = 0; ii < 8; ii++)
                #pragma unroll
                for (int jj = 0; jj < 8; jj++)
                    acc[ii][jj] += av[ii] * bv[jj];
        }
        __syncthreads();
    }

    // epilogue: l2 -> 5 gaussians -> signed partial sum
    float si[8], sj[8];
    #pragma unroll
    for (int ii = 0; ii < 8; ii++) si[ii] = g_sq[i0 + ty * 8 + ii];
    #pragma unroll
    for (int jj = 0; jj < 8; jj++) sj[jj] = g_sq[j0 + tx * 8 + jj];

    const float c0f = g_c[0], c1f = g_c[1], c2f = g_c[2], c3f = g_c[3], c4f = g_c[4];

    float part = 0.0f;
    #pragma unroll
    for (int ii = 0; ii < 8; ii++) {
        #pragma unroll
        for (int jj = 0; jj < 8; jj++) {
            float nl2 = 2.0f * acc[ii][jj] - si[ii] - sj[jj];   // = -l2
            float ks  = ex2(nl2 * c0f) + ex2(nl2 * c1f) + ex2(nl2 * c2f)
                      + ex2(nl2 * c3f) + ex2(nl2 * c4f);
            part += ks;
        }
    }

    // tile-level sign and symmetry weight
    float w = (ti == tj) ? 1.0f : 2.0f;
    float sg = ((ti < NTILES / 2) == (tj < NTILES / 2)) ? 1.0f : -1.0f;
    part *= w * sg;

    __shared__ float rbuf[256];
    rbuf[tid] = part;
    __syncthreads();
    #pragma unroll
    for (int s = 128; s > 0; s >>= 1) {
        if (tid < s) rbuf[tid] += rbuf[tid + s];
        __syncthreads();
    }
    if (tid == 0) atomicAdd(&g_acc, (double)rbuf[0]);
}

__global__ void writeout_kernel(float* __restrict__ out) {
    out[0] = (float)(g_acc / ((double)NS * (double)NS));
}

// ---------------------------------------------------------------------------
extern "C" void kernel_launch(void* const* d_in, const int* in_sizes, int n_in,
                              void* d_out, int out_size) {
    const float* src = (const float*)d_in[0];
    const float* tgt = (const float*)d_in[1];
    float* out = (float*)d_out;

    init_kernel<<<1, 256>>>();
    prep_kernel<<<256, 256>>>(src, tgt);
    finalize_kernel<<<1, 256>>>();
    dim3 grid(NTILES, NTILES);
    mmd_kernel<<<grid, 256>>>(src, tgt);
    writeout_kernel<<<1, 1>>>(out);
}

// round 3
// speedup vs baseline: 3.1059x; 3.1059x over previous
#include <cuda_runtime.h>
#include <cstdint>

// ---------------------------------------------------------------------------
// MMD loss via mma.sync tf32 gram + fused gaussian epilogue.
//   loss = (1/ns^2) * sum_{i,j} s_i s_j K_ij
//   K_ij = u + u^2 + u^4 + u^8 + u^16,  u = 2^(-l2_ij * c4),  c4 = log2e/(bw*16)
//   l2_ij = sq_i + sq_j - 2 g_ij ; bandwidth from O(nD) identity.
//   Symmetry: tiles tj >= ti only, off-diagonal weight 2.
// ---------------------------------------------------------------------------

#define NS     4096
#define DDIM   256
#define NTOT   8192
#define BM     128
#define BKC    64
#define NCHUNK (DDIM / BKC)     // 4
#define NTILES (NTOT / BM)      // 64
#define SSTR   68               // smem row stride (floats): 4g+t conflict-free

// smem byte offsets (dynamic smem)
#define SM_A    0
#define SM_B    34816           // 128*68*4
#define SM_SQI  69632
#define SM_SQJ  70144
#define SM_RED  70656
#define SMEM_BYTES 71680

__device__ float  g_sq[NTOT];
__device__ float  g_colsum[DDIM];
__device__ double g_acc;
__device__ float  g_c4;

// ---------------------------------------------------------------------------
__device__ __forceinline__ float ex2f(float x) {
    float r; asm("ex2.approx.ftz.f32 %0, %1;" : "=f"(r) : "f"(x)); return r;
}
__device__ __forceinline__ uint32_t to_tf32_bits(float x) {
    float r; asm("cvt.rna.tf32.f32 %0, %1;" : "=f"(r) : "f"(x));
    return __float_as_uint(r);
}
__device__ __forceinline__ void mma_tf32(float c[4],
                                         uint32_t a0, uint32_t a1,
                                         uint32_t a2, uint32_t a3,
                                         uint32_t b0, uint32_t b1) {
    asm volatile(
        "mma.sync.aligned.m16n8k8.row.col.f32.tf32.tf32.f32 "
        "{%0,%1,%2,%3},{%4,%5,%6,%7},{%8,%9},{%0,%1,%2,%3};"
        : "+f"(c[0]), "+f"(c[1]), "+f"(c[2]), "+f"(c[3])
        : "r"(a0), "r"(a1), "r"(a2), "r"(a3), "r"(b0), "r"(b1));
}

// ---------------------------------------------------------------------------
__global__ void init_kernel() {
    int t = threadIdx.x;
    if (t < DDIM) g_colsum[t] = 0.0f;
    if (t == 0)   g_acc = 0.0;
}

__global__ void rowsq_kernel(const float* __restrict__ src,
                             const float* __restrict__ tgt) {
    int w    = threadIdx.x >> 5;
    int lane = threadIdx.x & 31;
    int row  = blockIdx.x * 8 + w;
    const float* p = (row < NS) ? (src + (size_t)row * DDIM)
                                : (tgt + (size_t)(row - NS) * DDIM);
    float4 a = *(const float4*)(p + lane * 8);
    float4 b = *(const float4*)(p + lane * 8 + 4);
    float s = a.x*a.x + a.y*a.y + a.z*a.z + a.w*a.w
            + b.x*b.x + b.y*b.y + b.z*b.z + b.w*b.w;
    #pragma unroll
    for (int o = 16; o > 0; o >>= 1) s += __shfl_xor_sync(0xFFFFFFFFu, s, o);
    if (lane == 0) g_sq[row] = s;
}

__global__ void colsum_kernel(const float* __restrict__ src,
                              const float* __restrict__ tgt) {
    int t = threadIdx.x;
    int b = blockIdx.x;
    float acc = 0.0f;
    for (int rr = 0; rr < 32; rr++) {
        int row = b * 32 + rr;
        const float* p = (row < NS) ? (src + (size_t)row * DDIM)
                                    : (tgt + (size_t)(row - NS) * DDIM);
        acc += p[t];
    }
    atomicAdd(&g_colsum[t], acc);
}

__global__ void finalize_kernel() {
    const int t = threadIdx.x;
    __shared__ double red[256];

    double s = 0.0;
    for (int i = t; i < NTOT; i += 256) s += (double)g_sq[i];
    red[t] = s;
    __syncthreads();
    #pragma unroll
    for (int st = 128; st > 0; st >>= 1) {
        if (t < st) red[t] += red[t + st];
        __syncthreads();
    }
    double S = red[0];
    __syncthreads();

    double c = (double)g_colsum[t];
    red[t] = c * c;
    __syncthreads();
    #pragma unroll
    for (int st = 128; st > 0; st >>= 1) {
        if (t < st) red[t] += red[t + st];
        __syncthreads();
    }

    if (t == 0) {
        double V      = red[0];
        double n      = (double)NTOT;
        double sum_l2 = 2.0 * n * S - 2.0 * V;
        double bw     = sum_l2 / (n * n - n);
        bw /= 4.0;                                    // KERNEL_MUL^(NUM//2)
        const double LOG2E = 1.4426950408889634;
        // c4: coefficient of the WIDEST bandwidth (bw * 2^4)
        g_c4 = (float)(LOG2E / (bw * 16.0));
    }
}

// ---------------------------------------------------------------------------
// Fused tile kernel: 128x128 pair tile, mma.sync tf32 gram, gaussian epilogue.
// 8 warps: warp_m = wid&1 (64 rows), warp_n = wid>>1 (32 cols).
__global__ void __launch_bounds__(256, 2)
mmd_kernel(const float* __restrict__ src, const float* __restrict__ tgt) {
    const int ti = blockIdx.y;
    const int tj = blockIdx.x;
    if (tj < ti) return;

    extern __shared__ char smem[];
    uint32_t* As = (uint32_t*)(smem + SM_A);
    uint32_t* Bs = (uint32_t*)(smem + SM_B);
    float*   sqi = (float*)(smem + SM_SQI);
    float*   sqj = (float*)(smem + SM_SQJ);
    float*   red = (float*)(smem + SM_RED);

    const int tid  = threadIdx.x;
    const int wid  = tid >> 5;
    const int lane = tid & 31;
    const int g    = lane >> 2;    // group id 0..7
    const int t4   = lane & 3;     // thread-in-group 0..3
    const int wm   = wid & 1;      // warp m index
    const int wn   = wid >> 1;     // warp n index

    const int i0 = ti * BM;
    const int j0 = tj * BM;
    const float* Abase = (i0 < NS) ? (src + (size_t)i0 * DDIM)
                                   : (tgt + (size_t)(i0 - NS) * DDIM);
    const float* Bbase = (j0 < NS) ? (src + (size_t)j0 * DDIM)
                                   : (tgt + (size_t)(j0 - NS) * DDIM);

    if (tid < 128) sqi[tid]       = g_sq[i0 + tid];
    else           sqj[tid - 128] = g_sq[j0 + tid - 128];

    float acc[4][4][4];
    #pragma unroll
    for (int a = 0; a < 4; a++)
        #pragma unroll
        for (int b = 0; b < 4; b++)
            #pragma unroll
            for (int f = 0; f < 4; f++) acc[a][b][f] = 0.0f;

    for (int ch = 0; ch < NCHUNK; ch++) {
        const int kk = ch * BKC;
        // load 128x64 f32 of A and B -> tf32 bits -> smem (stride SSTR)
        #pragma unroll
        for (int l = 0; l < 8; l++) {
            int idx = tid + l * 256;          // 0..2047
            int r   = idx >> 4;               // row 0..127
            int c   = idx & 15;               // float4 col 0..15
            float4 va = *(const float4*)(Abase + r * DDIM + kk + c * 4);
            float4 vb = *(const float4*)(Bbase + r * DDIM + kk + c * 4);
            uint32_t* pa = &As[r * SSTR + c * 4];
            uint32_t* pb = &Bs[r * SSTR + c * 4];
            pa[0] = to_tf32_bits(va.x); pa[1] = to_tf32_bits(va.y);
            pa[2] = to_tf32_bits(va.z); pa[3] = to_tf32_bits(va.w);
            pb[0] = to_tf32_bits(vb.x); pb[1] = to_tf32_bits(vb.y);
            pb[2] = to_tf32_bits(vb.z); pb[3] = to_tf32_bits(vb.w);
        }
        __syncthreads();

        #pragma unroll
        for (int s = 0; s < BKC / 8; s++) {
            const int kb = s * 8;
            uint32_t af[4][4], bf[4][2];
            #pragma unroll
            for (int ma = 0; ma < 4; ma++) {
                int r0 = wm * 64 + ma * 16 + g;
                const uint32_t* p0 = &As[r0 * SSTR + kb + t4];
                const uint32_t* p1 = &As[(r0 + 8) * SSTR + kb + t4];
                af[ma][0] = p0[0]; af[ma][1] = p1[0];
                af[ma][2] = p0[4]; af[ma][3] = p1[4];
            }
            #pragma unroll
            for (int nb = 0; nb < 4; nb++) {
                int c0 = wn * 32 + nb * 8 + g;
                const uint32_t* p = &Bs[c0 * SSTR + kb + t4];
                bf[nb][0] = p[0]; bf[nb][1] = p[4];
            }
            #pragma unroll
            for (int ma = 0; ma < 4; ma++)
                #pragma unroll
                for (int nb = 0; nb < 4; nb++)
                    mma_tf32(acc[ma][nb], af[ma][0], af[ma][1], af[ma][2],
                             af[ma][3], bf[nb][0], bf[nb][1]);
        }
        __syncthreads();
    }

    // --- epilogue ---
    const float c4 = g_c4;
    float si[4][2], sj[4][2];
    #pragma unroll
    for (int ma = 0; ma < 4; ma++) {
        si[ma][0] = sqi[wm * 64 + ma * 16 + g];
        si[ma][1] = sqi[wm * 64 + ma * 16 + g + 8];
    }
    #pragma unroll
    for (int nb = 0; nb < 4; nb++) {
        sj[nb][0] = sqj[wn * 32 + nb * 8 + 2 * t4];
        sj[nb][1] = sqj[wn * 32 + nb * 8 + 2 * t4 + 1];
    }

    float part = 0.0f;
    #pragma unroll
    for (int ma = 0; ma < 4; ma++) {
        #pragma unroll
        for (int nb = 0; nb < 4; nb++) {
            #pragma unroll
            for (int f = 0; f < 4; f++) {
                float nl2 = 2.0f * acc[ma][nb][f] - si[ma][f >> 1] - sj[nb][f & 1];
                float u   = ex2f(nl2 * c4);        // widest-bw gaussian
                float u2  = u  * u;
                float u4  = u2 * u2;
                float u8  = u4 * u4;
                float u16 = u8 * u8;
                part += (u + u2) + (u4 + u8) + u16;
            }
        }
    }

    float w  = (ti == tj) ? 1.0f : 2.0f;
    float sg = ((ti < NTILES / 2) == (tj < NTILES / 2)) ? 1.0f : -1.0f;
    part *= w * sg;

    red[tid] = part;
    __syncthreads();
    #pragma unroll
    for (int s = 128; s > 0; s >>= 1) {
        if (tid < s) red[tid] += red[tid + s];
        __syncthreads();
    }
    if (tid == 0) atomicAdd(&g_acc, (double)red[0]);
}

__global__ void writeout_kernel(float* __restrict__ out) {
    out[0] = (float)(g_acc / ((double)NS * (double)NS));
}

// ---------------------------------------------------------------------------
extern "C" void kernel_launch(void* const* d_in, const int* in_sizes, int n_in,
                              void* d_out, int out_size) {
    const float* src = (const float*)d_in[0];
    const float* tgt = (const float*)d_in[1];
    float* out = (float*)d_out;

    cudaFuncSetAttribute(mmd_kernel,
                         cudaFuncAttributeMaxDynamicSharedMemorySize, SMEM_BYTES);

    init_kernel<<<1, 256>>>();
    rowsq_kernel<<<NTOT / 8, 256>>>(src, tgt);
    colsum_kernel<<<256, 256>>>(src, tgt);
    finalize_kernel<<<1, 256>>>();
    dim3 grid(NTILES, NTILES);
    mmd_kernel<<<grid, 256, SMEM_BYTES>>>(src, tgt);
    writeout_kernel<<<1, 1>>>(out);
}

// round 6
// speedup vs baseline: 3.3974x; 1.0938x over previous
#include <cuda_runtime.h>
#include <cstdint>

// ---------------------------------------------------------------------------
// MMD loss via mma.sync tf32 gram (cp.async 3-stage pipeline) + fused epilogue
//   loss = (1/ns^2) * sum_{i,j} s_i s_j K_ij
//   K_ij = u + u^2 + u^4 + u^8 + u^16,  u = 2^(-l2_ij*c4), c4 = log2e/(bw*16)
//   l2_ij = sq_i + sq_j - 2 g_ij ; bandwidth via O(nD) identity.
//   Inputs are pre-rounded (cvt.rna.tf32) into g_conv so the HW MMA's
//   fp32->tf32 truncation is exact (unbiased rounding, R3-verified accuracy).
//   Symmetry: tiles tj >= ti only, off-diagonal weight 2.
// ---------------------------------------------------------------------------

#define NS     4096
#define DDIM   256
#define NTOT   8192
#define BM     128
#define BKC    32
#define NCHUNK (DDIM / BKC)     // 8
#define NTILES (NTOT / BM)      // 64
#define SSTR   36               // smem row stride (floats): 4r+t conflict-free
#define ROWB   (SSTR * 4)       // 144 bytes per row
#define ASZ    (BM * ROWB)      // 18432 bytes per stage per matrix

// smem byte offsets
#define SM_A0   0               // 3 stages of A
#define SM_B0   (3 * ASZ)       // 3 stages of B
#define SM_SQI  (6 * ASZ)       // 110592
#define SM_SQJ  (SM_SQI + 512)
#define SM_RED  (SM_SQI + 1024)
#define SMEM_BYTES (SM_SQI + 2048)   // 112640 -> 2 CTAs/SM

__device__ float  g_conv[NTOT * DDIM];   // tf32-rounded inputs (8 MB)
__device__ float  g_sq[NTOT];
__device__ float  g_colsum[DDIM];
__device__ double g_ssum;
__device__ double g_acc;
__device__ float  g_c4;

// ---------------------------------------------------------------------------
__device__ __forceinline__ float ex2f(float x) {
    float r; asm("ex2.approx.ftz.f32 %0, %1;" : "=f"(r) : "f"(x)); return r;
}
__device__ __forceinline__ float to_tf32(float x) {
    float r; asm("cvt.rna.tf32.f32 %0, %1;" : "=f"(r) : "f"(x)); return r;
}
__device__ __forceinline__ uint32_t smem_u32(const void* p) {
    uint32_t a;
    asm("{ .reg .u64 t; cvta.to.shared.u64 t, %1; cvt.u32.u64 %0, t; }"
        : "=r"(a) : "l"(p));
    return a;
}
__device__ __forceinline__ void cp16(uint32_t dst, const float* src) {
    asm volatile("cp.async.cg.shared.global [%0], [%1], 16;"
                 :: "r"(dst), "l"(src));
}
__device__ __forceinline__ void cp_commit() {
    asm volatile("cp.async.commit_group;" ::: "memory");
}
template <int N>
__device__ __forceinline__ void cp_wait() {
    asm volatile("cp.async.wait_group %0;" :: "n"(N) : "memory");
}
__device__ __forceinline__ void mma_tf32(float c[4],
                                         uint32_t a0, uint32_t a1,
                                         uint32_t a2, uint32_t a3,
                                         uint32_t b0, uint32_t b1) {
    asm volatile(
        "mma.sync.aligned.m16n8k8.row.col.f32.tf32.tf32.f32 "
        "{%0,%1,%2,%3},{%4,%5,%6,%7},{%8,%9},{%0,%1,%2,%3};"
        : "+f"(c[0]), "+f"(c[1]), "+f"(c[2]), "+f"(c[3])
        : "r"(a0), "r"(a1), "r"(a2), "r"(a3), "r"(b0), "r"(b1));
}

// ---------------------------------------------------------------------------
__global__ void init_kernel() {
    int t = threadIdx.x;
    if (t < DDIM) g_colsum[t] = 0.0f;
    if (t == 0) { g_acc = 0.0; g_ssum = 0.0; }
}

// 256 blocks x 256 thr; block b owns rows [b*32, b*32+32).
// Warp-per-row: sumsq + tf32-round + store to g_conv; then colsum pass.
__global__ void prep_kernel(const float* __restrict__ src,
                            const float* __restrict__ tgt) {
    const int tid  = threadIdx.x;
    const int w    = tid >> 5;
    const int lane = tid & 31;
    const int b    = blockIdx.x;
    const float* base = (b < 128) ? (src + (size_t)b * 32 * DDIM)
                                  : (tgt + (size_t)(b - 128) * 32 * DDIM);
    float* conv = g_conv + (size_t)b * 32 * DDIM;
    __shared__ float wsum[8];

    float mysq = 0.0f;
    #pragma unroll
    for (int it = 0; it < 4; it++) {
        int r = it * 8 + w;
        const float* p = base + (size_t)r * DDIM;
        float4 a = *(const float4*)(p + lane * 8);
        float4 c = *(const float4*)(p + lane * 8 + 4);
        float s = a.x*a.x + a.y*a.y + a.z*a.z + a.w*a.w
                + c.x*c.x + c.y*c.y + c.z*c.z + c.w*c.w;
        // tf32-round and store
        float4 ra = make_float4(to_tf32(a.x), to_tf32(a.y),
                                to_tf32(a.z), to_tf32(a.w));
        float4 rc = make_float4(to_tf32(c.x), to_tf32(c.y),
                                to_tf32(c.z), to_tf32(c.w));
        *(float4*)(conv + (size_t)r * DDIM + lane * 8)     = ra;
        *(float4*)(conv + (size_t)r * DDIM + lane * 8 + 4) = rc;
        #pragma unroll
        for (int o = 16; o > 0; o >>= 1) s += __shfl_xor_sync(0xFFFFFFFFu, s, o);
        if (lane == 0) { g_sq[b * 32 + r] = s; mysq += s; }
    }
    if (lane == 0) wsum[w] = mysq;

    // column sums: thread t accumulates column t over 32 rows
    float cs = 0.0f;
    #pragma unroll 8
    for (int r = 0; r < 32; r++) cs += base[(size_t)r * DDIM + tid];
    atomicAdd(&g_colsum[tid], cs);

    __syncthreads();
    if (tid == 0) {
        float tot = 0.0f;
        #pragma unroll
        for (int i = 0; i < 8; i++) tot += wsum[i];
        atomicAdd(&g_ssum, (double)tot);
    }
}

__global__ void finalize_kernel() {
    const int t    = threadIdx.x;
    const int w    = t >> 5;
    const int lane = t & 31;
    __shared__ double wred[8];

    float c = g_colsum[t];
    double v = (double)c * (double)c;
    #pragma unroll
    for (int o = 16; o > 0; o >>= 1)
        v += __shfl_xor_sync(0xFFFFFFFFu, v, o);
    if (lane == 0) wred[w] = v;
    __syncthreads();
    if (t == 0) {
        double V = 0.0;
        #pragma unroll
        for (int i = 0; i < 8; i++) V += wred[i];
        double S      = g_ssum;
        double n      = (double)NTOT;
        double sum_l2 = 2.0 * n * S - 2.0 * V;
        double bw     = sum_l2 / (n * n - n);
        bw /= 4.0;                                   // KERNEL_MUL^(NUM//2)
        g_c4 = (float)(1.4426950408889634 / (bw * 16.0));
    }
}

// ---------------------------------------------------------------------------
// Fused tile kernel: 128x128 tile, cp.async 3-stage pipeline, tf32 mma gram.
__global__ void __launch_bounds__(256, 2)
mmd_kernel() {
    const int ti = blockIdx.y;
    const int tj = blockIdx.x;
    if (tj < ti) return;

    extern __shared__ char smem[];
    const uint32_t sbase = smem_u32(smem);
    float* sqi = (float*)(smem + SM_SQI);
    float* sqj = (float*)(smem + SM_SQJ);
    float* red = (float*)(smem + SM_RED);

    const int tid  = threadIdx.x;
    const int wid  = tid >> 5;
    const int lane = tid & 31;
    const int g    = lane >> 2;
    const int t4   = lane & 3;
    const int wm   = wid & 1;
    const int wn   = wid >> 1;

    const int i0 = ti * BM;
    const int j0 = tj * BM;
    const float* Abase = g_conv + (size_t)i0 * DDIM;
    const float* Bbase = g_conv + (size_t)j0 * DDIM;

    if (tid < 128) sqi[tid]       = g_sq[i0 + tid];
    else           sqj[tid - 128] = g_sq[j0 + tid - 128];

    // per-thread cp.async coordinates (4 x 16B per matrix per chunk)
    const int pr = tid >> 3;          // row group base 0..31
    const int pq = tid & 7;           // 16B column 0..7

    // prologue: prefetch chunks 0,1
    #pragma unroll
    for (int c = 0; c < 2; c++) {
        const int kk = c * BKC;
        #pragma unroll
        for (int l = 0; l < 4; l++) {
            int r = pr + l * 32;
            cp16(sbase + SM_A0 + c * ASZ + r * ROWB + pq * 16,
                 Abase + (size_t)r * DDIM + kk + pq * 4);
            cp16(sbase + SM_B0 + c * ASZ + r * ROWB + pq * 16,
                 Bbase + (size_t)r * DDIM + kk + pq * 4);
        }
        cp_commit();
    }

    float acc[4][4][4];
    #pragma unroll
    for (int a = 0; a < 4; a++)
        #pragma unroll
        for (int b = 0; b < 4; b++)
            #pragma unroll
            for (int f = 0; f < 4; f++) acc[a][b][f] = 0.0f;

    int st_c = 0, st_p = 2;           // compute stage, prefetch stage
    #pragma unroll 1
    for (int c = 0; c < NCHUNK; c++) {
        if (c + 2 < NCHUNK) {
            const int kk = (c + 2) * BKC;
            #pragma unroll
            for (int l = 0; l < 4; l++) {
                int r = pr + l * 32;
                cp16(sbase + SM_A0 + st_p * ASZ + r * ROWB + pq * 16,
                     Abase + (size_t)r * DDIM + kk + pq * 4);
                cp16(sbase + SM_B0 + st_p * ASZ + r * ROWB + pq * 16,
                     Bbase + (size_t)r * DDIM + kk + pq * 4);
            }
            cp_commit();
            cp_wait<2>();
        } else if (c + 1 < NCHUNK) {
            cp_wait<1>();
        } else {
            cp_wait<0>();
        }
        __syncthreads();

        const uint32_t* As = (const uint32_t*)(smem + SM_A0 + st_c * ASZ);
        const uint32_t* Bs = (const uint32_t*)(smem + SM_B0 + st_c * ASZ);

        #pragma unroll
        for (int s = 0; s < BKC / 8; s++) {
            const int kb = s * 8;
            uint32_t af[4][4], bf[4][2];
            #pragma unroll
            for (int ma = 0; ma < 4; ma++) {
                int r0 = wm * 64 + ma * 16 + g;
                const uint32_t* p0 = &As[r0 * SSTR + kb + t4];
                const uint32_t* p1 = &As[(r0 + 8) * SSTR + kb + t4];
                af[ma][0] = p0[0]; af[ma][1] = p1[0];
                af[ma][2] = p0[4]; af[ma][3] = p1[4];
            }
            #pragma unroll
            for (int nb = 0; nb < 4; nb++) {
                int c0 = wn * 32 + nb * 8 + g;
                const uint32_t* p = &Bs[c0 * SSTR + kb + t4];
                bf[nb][0] = p[0]; bf[nb][1] = p[4];
            }
            #pragma unroll
            for (int ma = 0; ma < 4; ma++)
                #pragma unroll
                for (int nb = 0; nb < 4; nb++)
                    mma_tf32(acc[ma][nb], af[ma][0], af[ma][1], af[ma][2],
                             af[ma][3], bf[nb][0], bf[nb][1]);
        }
        __syncthreads();

        st_c = (st_c == 2) ? 0 : st_c + 1;
        st_p = (st_p == 2) ? 0 : st_p + 1;
    }

    // --- epilogue ---
    const float c4 = g_c4;
    float si[4][2], sj[4][2];
    #pragma unroll
    for (int ma = 0; ma < 4; ma++) {
        si[ma][0] = sqi[wm * 64 + ma * 16 + g];
        si[ma][1] = sqi[wm * 64 + ma * 16 + g + 8];
    }
    #pragma unroll
    for (int nb = 0; nb < 4; nb++) {
        sj[nb][0] = sqj[wn * 32 + nb * 8 + 2 * t4];
        sj[nb][1] = sqj[wn * 32 + nb * 8 + 2 * t4 + 1];
    }

    float part = 0.0f;
    #pragma unroll
    for (int ma = 0; ma < 4; ma++) {
        #pragma unroll
        for (int nb = 0; nb < 4; nb++) {
            #pragma unroll
            for (int f = 0; f < 4; f++) {
                float nl2 = 2.0f * acc[ma][nb][f] - si[ma][f >> 1] - sj[nb][f & 1];
                float u   = ex2f(nl2 * c4);
                float u2  = u  * u;
                float u4  = u2 * u2;
                float u8  = u4 * u4;
                float u16 = u8 * u8;
                part += (u + u2) + (u4 + u8) + u16;
            }
        }
    }

    float w  = (ti == tj) ? 1.0f : 2.0f;
    float sg = ((ti < NTILES / 2) == (tj < NTILES / 2)) ? 1.0f : -1.0f;
    part *= w * sg;

    red[tid] = part;
    __syncthreads();
    #pragma unroll
    for (int s = 128; s > 0; s >>= 1) {
        if (tid < s) red[tid] += red[tid + s];
        __syncthreads();
    }
    if (tid == 0) atomicAdd(&g_acc, (double)red[0]);
}

__global__ void writeout_kernel(float* __restrict__ out) {
    out[0] = (float)(g_acc / ((double)NS * (double)NS));
}

// ---------------------------------------------------------------------------
extern "C" void kernel_launch(void* const* d_in, const int* in_sizes, int n_in,
                              void* d_out, int out_size) {
    const float* src = (const float*)d_in[0];
    const float* tgt = (const float*)d_in[1];
    float* out = (float*)d_out;

    cudaFuncSetAttribute(mmd_kernel,
                         cudaFuncAttributeMaxDynamicSharedMemorySize, SMEM_BYTES);

    init_kernel<<<1, 256>>>();
    prep_kernel<<<256, 256>>>(src, tgt);
    finalize_kernel<<<1, 256>>>();
    dim3 grid(NTILES, NTILES);
    mmd_kernel<<<grid, 256, SMEM_BYTES>>>();
    writeout_kernel<<<1, 1>>>(out);
}

// round 7
// speedup vs baseline: 4.0864x; 1.2028x over previous
#include <cuda_runtime.h>
#include <cstdint>

// ---------------------------------------------------------------------------
// MMD loss via mma.sync tf32 gram + fused gaussian epilogue.
//   loss = (1/ns^2) * sum_{i,j} s_i s_j K_ij
//   K_ij = u + u^2 + u^4 + u^8 + u^16,  u = 2^(-l2_ij*c4), c4 = log2e/(bw*16)
//   l2_ij = sq_i + sq_j - 2 g_ij ; bandwidth via O(nD) identity.
// Inputs pre-rounded to tf32 AND pre-permuted into MMA fragment order:
//   g_convA: per 16-row x 8-k block, float4 {a0,a1,a2,a3} per (g,t4) lane
//   g_convB: per 8-col x 8-k block, float2 {b0,b1} per (g,t4) lane
// so mainloop fragment loads are single LDS.128 / LDS.64, conflict-free.
// Symmetry: tiles tj >= ti only, off-diagonal weight 2.
// ---------------------------------------------------------------------------

#define NS     4096
#define DDIM   256
#define NTOT   8192
#define BM     128
#define BKC    32
#define NCHUNK (DDIM / BKC)     // 8
#define NTILES (NTOT / BM)      // 64

#define ASTG   16384            // A stage bytes: 8 rowblocks x 2048
#define BSTG   16384            // B stage bytes: 16 colblocks x 1024

// smem byte offsets (3 stages each)
#define SM_A0   0
#define SM_B0   (3 * ASTG)      // 49152
#define SM_SQI  (6 * ASTG)      // 98304
#define SM_SQJ  (SM_SQI + 512)
#define SM_RED  (SM_SQI + 1024)
#define SMEM_BYTES (SM_SQI + 2048)   // 100352 -> 2 CTAs/SM

__device__ float  g_convA[NTOT * DDIM];  // A-fragment order, 8 MB
__device__ float  g_convB[NTOT * DDIM];  // B-fragment order, 8 MB
__device__ float  g_sq[NTOT];
__device__ float  g_colsum[DDIM];
__device__ double g_ssum;
__device__ double g_acc;
__device__ float  g_c4;

// ---------------------------------------------------------------------------
__device__ __forceinline__ float ex2f(float x) {
    float r; asm("ex2.approx.ftz.f32 %0, %1;" : "=f"(r) : "f"(x)); return r;
}
__device__ __forceinline__ float to_tf32(float x) {
    float r; asm("cvt.rna.tf32.f32 %0, %1;" : "=f"(r) : "f"(x)); return r;
}
__device__ __forceinline__ uint32_t smem_u32(const void* p) {
    uint32_t a;
    asm("{ .reg .u64 t; cvta.to.shared.u64 t, %1; cvt.u32.u64 %0, t; }"
        : "=r"(a) : "l"(p));
    return a;
}
__device__ __forceinline__ void cp16(uint32_t dst, const float* src) {
    asm volatile("cp.async.cg.shared.global [%0], [%1], 16;"
                 :: "r"(dst), "l"(src));
}
__device__ __forceinline__ void cp_commit() {
    asm volatile("cp.async.commit_group;" ::: "memory");
}
template <int N>
__device__ __forceinline__ void cp_wait() {
    asm volatile("cp.async.wait_group %0;" :: "n"(N) : "memory");
}
__device__ __forceinline__ void mma_tf32(float c[4], const float4 a,
                                         const float2 b) {
    asm volatile(
        "mma.sync.aligned.m16n8k8.row.col.f32.tf32.tf32.f32 "
        "{%0,%1,%2,%3},{%4,%5,%6,%7},{%8,%9},{%0,%1,%2,%3};"
        : "+f"(c[0]), "+f"(c[1]), "+f"(c[2]), "+f"(c[3])
        : "r"(__float_as_uint(a.x)), "r"(__float_as_uint(a.y)),
          "r"(__float_as_uint(a.z)), "r"(__float_as_uint(a.w)),
          "r"(__float_as_uint(b.x)), "r"(__float_as_uint(b.y)));
}
__device__ __forceinline__ const float* srow(const float* __restrict__ src,
                                             const float* __restrict__ tgt,
                                             int row) {
    return (row < NS) ? (src + (size_t)row * DDIM)
                      : (tgt + (size_t)(row - NS) * DDIM);
}

// ---------------------------------------------------------------------------
__global__ void init_kernel() {
    int t = threadIdx.x;
    if (t < DDIM) g_colsum[t] = 0.0f;
    if (t == 0) { g_acc = 0.0; g_ssum = 0.0; }
}

// prep: sumsq per row + colsums (reads raw src/tgt).
__global__ void prep_kernel(const float* __restrict__ src,
                            const float* __restrict__ tgt) {
    const int tid  = threadIdx.x;
    const int w    = tid >> 5;
    const int lane = tid & 31;
    const int b    = blockIdx.x;
    const float* base = (b < 128) ? (src + (size_t)b * 32 * DDIM)
                                  : (tgt + (size_t)(b - 128) * 32 * DDIM);
    __shared__ float wsum[8];

    float mysq = 0.0f;
    #pragma unroll
    for (int it = 0; it < 4; it++) {
        int r = it * 8 + w;
        const float* p = base + (size_t)r * DDIM;
        float4 a = *(const float4*)(p + lane * 8);
        float4 c = *(const float4*)(p + lane * 8 + 4);
        float s = a.x*a.x + a.y*a.y + a.z*a.z + a.w*a.w
                + c.x*c.x + c.y*c.y + c.z*c.z + c.w*c.w;
        #pragma unroll
        for (int o = 16; o > 0; o >>= 1) s += __shfl_xor_sync(0xFFFFFFFFu, s, o);
        if (lane == 0) { g_sq[b * 32 + r] = s; mysq += s; }
    }
    if (lane == 0) wsum[w] = mysq;

    float cs = 0.0f;
    #pragma unroll 8
    for (int r = 0; r < 32; r++) cs += base[(size_t)r * DDIM + tid];
    atomicAdd(&g_colsum[tid], cs);

    __syncthreads();
    if (tid == 0) {
        float tot = 0.0f;
        #pragma unroll
        for (int i = 0; i < 8; i++) tot += wsum[i];
        atomicAdd(&g_ssum, (double)tot);
    }
}

// permute: build g_convA (float4 frags) and g_convB (float2 frags).
// blocks [0, 2048): A-copy, 1 float4/thread. blocks [2048, 6144): B-copy.
__global__ void permute_kernel(const float* __restrict__ src,
                               const float* __restrict__ tgt) {
    if (blockIdx.x < 2048) {
        int o   = blockIdx.x * 256 + threadIdx.x;   // float4 index
        int R   = o >> 10;                          // row-block (16 rows)
        int rem = o & 1023;
        int C   = rem >> 7;                         // 32-k chunk
        int c8  = (rem >> 5) & 3;                   // 8-k sub
        int fi  = rem & 31;
        int g   = fi >> 2;
        int t4  = fi & 3;
        int r   = R * 16 + g;
        int k   = C * 32 + c8 * 8 + t4;
        const float* p0 = srow(src, tgt, r);
        const float* p1 = srow(src, tgt, r + 8);
        float4 v = make_float4(to_tf32(p0[k]),     to_tf32(p1[k]),
                               to_tf32(p0[k + 4]), to_tf32(p1[k + 4]));
        *(float4*)(g_convA + (size_t)o * 4) = v;
    } else {
        int o   = (blockIdx.x - 2048) * 256 + threadIdx.x;  // float2 index
        int CB  = o >> 10;                          // col-block (8 cols)
        int rem = o & 1023;
        int C   = rem >> 7;
        int c8  = (rem >> 5) & 3;
        int fi  = rem & 31;
        int g   = fi >> 2;
        int t4  = fi & 3;
        int c   = CB * 8 + g;
        int k   = C * 32 + c8 * 8 + t4;
        const float* p = srow(src, tgt, c);
        float2 v = make_float2(to_tf32(p[k]), to_tf32(p[k + 4]));
        *(float2*)(g_convB + (size_t)o * 2) = v;
    }
}

__global__ void finalize_kernel() {
    const int t    = threadIdx.x;
    const int w    = t >> 5;
    const int lane = t & 31;
    __shared__ double wred[8];

    float c = g_colsum[t];
    double v = (double)c * (double)c;
    #pragma unroll
    for (int o = 16; o > 0; o >>= 1)
        v += __shfl_xor_sync(0xFFFFFFFFu, v, o);
    if (lane == 0) wred[w] = v;
    __syncthreads();
    if (t == 0) {
        double V = 0.0;
        #pragma unroll
        for (int i = 0; i < 8; i++) V += wred[i];
        double S      = g_ssum;
        double n      = (double)NTOT;
        double sum_l2 = 2.0 * n * S - 2.0 * V;
        double bw     = sum_l2 / (n * n - n);
        bw /= 4.0;
        g_c4 = (float)(1.4426950408889634 / (bw * 16.0));
    }
}

// ---------------------------------------------------------------------------
// Fused tile kernel: 128x128 tile, fragment-ordered smem, 3-stage cp.async.
__global__ void __launch_bounds__(256, 2)
mmd_kernel() {
    const int ti = blockIdx.y;
    const int tj = blockIdx.x;
    if (tj < ti) return;

    extern __shared__ char smem[];
    const uint32_t sbase = smem_u32(smem);
    float* sqi = (float*)(smem + SM_SQI);
    float* sqj = (float*)(smem + SM_SQJ);
    float* red = (float*)(smem + SM_RED);

    const int tid  = threadIdx.x;
    const int wid  = tid >> 5;
    const int lane = tid & 31;
    const int g    = lane >> 2;
    const int t4   = lane & 3;
    const int wm   = wid & 1;
    const int wn   = wid >> 1;

    const int i0 = ti * BM;
    const int j0 = tj * BM;
    const int Rb = ti * 8;      // A row-block base (16-row blocks)
    const int Cb = tj * 16;     // B col-block base (8-col blocks)

    if (tid < 128) sqi[tid]       = g_sq[i0 + tid];
    else           sqj[tid - 128] = g_sq[j0 + tid - 128];

    // prologue: prefetch chunks 0,1
    #pragma unroll
    for (int c = 0; c < 2; c++) {
        #pragma unroll
        for (int l = 0; l < 4; l++) {
            int ia = tid + l * 256;
            int rb = ia >> 7, wa = ia & 127;
            cp16(sbase + SM_A0 + c * ASTG + rb * 2048 + wa * 16,
                 g_convA + (size_t)((Rb + rb) * 8 + c) * 512 + wa * 4);
            int cb = ia >> 6 & 15, wb = ia & 63;
            int cb2 = ia >> 6;   // 0..15 over l*..; recompute cleanly below
            (void)cb; (void)cb2;
            cp16(sbase + SM_B0 + c * BSTG + (ia >> 6) * 1024 + wb * 16,
                 g_convB + (size_t)((Cb + (ia >> 6)) * 8 + c) * 256 + wb * 4);
        }
        cp_commit();
    }

    float acc[4][4][4];
    #pragma unroll
    for (int a = 0; a < 4; a++)
        #pragma unroll
        for (int b = 0; b < 4; b++)
            #pragma unroll
            for (int f = 0; f < 4; f++) acc[a][b][f] = 0.0f;

    int st_c = 0, st_p = 2;
    #pragma unroll 1
    for (int c = 0; c < NCHUNK; c++) {
        if (c + 2 < NCHUNK) {
            const int cc = c + 2;
            #pragma unroll
            for (int l = 0; l < 4; l++) {
                int ia = tid + l * 256;
                int rb = ia >> 7, wa = ia & 127;
                cp16(sbase + SM_A0 + st_p * ASTG + rb * 2048 + wa * 16,
                     g_convA + (size_t)((Rb + rb) * 8 + cc) * 512 + wa * 4);
                int wb = ia & 63;
                cp16(sbase + SM_B0 + st_p * BSTG + (ia >> 6) * 1024 + wb * 16,
                     g_convB + (size_t)((Cb + (ia >> 6)) * 8 + cc) * 256 + wb * 4);
            }
            cp_commit();
            cp_wait<2>();
        } else if (c + 1 < NCHUNK) {
            cp_wait<1>();
        } else {
            cp_wait<0>();
        }
        __syncthreads();

        const char* As = smem + SM_A0 + st_c * ASTG;
        const char* Bs = smem + SM_B0 + st_c * BSTG;

        #pragma unroll
        for (int s = 0; s < 4; s++) {
            float4 af[4];
            float2 bf[4];
            #pragma unroll
            for (int ma = 0; ma < 4; ma++)
                af[ma] = *(const float4*)(As + ((wm * 4 + ma) * 4 + s) * 512
                                             + lane * 16);
            #pragma unroll
            for (int nb = 0; nb < 4; nb++)
                bf[nb] = *(const float2*)(Bs + ((wn * 4 + nb) * 4 + s) * 256
                                             + lane * 8);
            #pragma unroll
            for (int ma = 0; ma < 4; ma++)
                #pragma unroll
                for (int nb = 0; nb < 4; nb++)
                    mma_tf32(acc[ma][nb], af[ma], bf[nb]);
        }
        __syncthreads();

        st_c = (st_c == 2) ? 0 : st_c + 1;
        st_p = (st_p == 2) ? 0 : st_p + 1;
    }

    // --- epilogue ---
    const float c4 = g_c4;
    float si[4][2], sj[4][2];
    #pragma unroll
    for (int ma = 0; ma < 4; ma++) {
        si[ma][0] = sqi[wm * 64 + ma * 16 + g];
        si[ma][1] = sqi[wm * 64 + ma * 16 + g + 8];
    }
    #pragma unroll
    for (int nb = 0; nb < 4; nb++) {
        sj[nb][0] = sqj[wn * 32 + nb * 8 + 2 * t4];
        sj[nb][1] = sqj[wn * 32 + nb * 8 + 2 * t4 + 1];
    }

    float part = 0.0f;
    #pragma unroll
    for (int ma = 0; ma < 4; ma++) {
        #pragma unroll
        for (int nb = 0; nb < 4; nb++) {
            #pragma unroll
            for (int f = 0; f < 4; f++) {
                float nl2 = 2.0f * acc[ma][nb][f] - si[ma][f >> 1] - sj[nb][f & 1];
                float u   = ex2f(nl2 * c4);
                float u2  = u  * u;
                float u4  = u2 * u2;
                float u8  = u4 * u4;
                float u16 = u8 * u8;
                part += (u + u2) + (u4 + u8) + u16;
            }
        }
    }

    float w  = (ti == tj) ? 1.0f : 2.0f;
    float sg = ((ti < NTILES / 2) == (tj < NTILES / 2)) ? 1.0f : -1.0f;
    part *= w * sg;

    red[tid] = part;
    __syncthreads();
    #pragma unroll
    for (int s = 128; s > 0; s >>= 1) {
        if (tid < s) red[tid] += red[tid + s];
        __syncthreads();
    }
    if (tid == 0) atomicAdd(&g_acc, (double)red[0]);
}

__global__ void writeout_kernel(float* __restrict__ out) {
    out[0] = (float)(g_acc / ((double)NS * (double)NS));
}

// ---------------------------------------------------------------------------
extern "C" void kernel_launch(void* const* d_in, const int* in_sizes, int n_in,
                              void* d_out, int out_size) {
    const float* src = (const float*)d_in[0];
    const float* tgt = (const float*)d_in[1];
    float* out = (float*)d_out;

    cudaFuncSetAttribute(mmd_kernel,
                         cudaFuncAttributeMaxDynamicSharedMemorySize, SMEM_BYTES);

    init_kernel<<<1, 256>>>();
    prep_kernel<<<256, 256>>>(src, tgt);
    permute_kernel<<<6144, 256>>>(src, tgt);
    finalize_kernel<<<1, 256>>>();
    dim3 grid(NTILES, NTILES);
    mmd_kernel<<<grid, 256, SMEM_BYTES>>>();
    writeout_kernel<<<1, 1>>>(out);
}

// round 8
// speedup vs baseline: 6.0208x; 1.4734x over previous
#include <cuda_runtime.h>
#include <cuda_fp16.h>
#include <cstdint>

// ---------------------------------------------------------------------------
// MMD loss via mma.sync fp16 gram (fp32 accum) + fused gaussian epilogue.
//   loss = (1/ns^2) * sum_{i,j} s_i s_j K_ij
//   K_ij = u + u^2 + u^4 + u^8 + u^16,  u = 2^(-l2_ij*c4), c4 = log2e/(bw*16)
//   l2_ij = sq_i + sq_j - 2 g_ij ; bandwidth via O(nD) identity (fp32 path).
// fp16 has the same 10-bit mantissa as tf32 (R3/6/7-verified accuracy) at 2x
// tensor throughput. Inputs pre-rounded (cvt.rn) and pre-permuted into
// m16n8k16 fragment order: A frag = 16B/lane (LDS.128), B = 8B/lane (LDS.64).
// Symmetry: triangular grid (2080 CTAs), off-diagonal tiles weight 2.
// ---------------------------------------------------------------------------

#define NS     4096
#define DDIM   256
#define NTOT   8192
#define BM     128
#define BKC    64
#define NCHUNK (DDIM / BKC)     // 4
#define NTILES (NTOT / BM)      // 64
#define NBLK   (NTILES * (NTILES + 1) / 2)   // 2080

#define ASTG   16384            // A stage: 8 rowblocks x 4 ksteps x 512B
#define BSTG   16384            // B stage: 16 colblocks x 4 ksteps x 256B

// smem byte offsets (3 stages each)
#define SM_A0   0
#define SM_B0   (3 * ASTG)      // 49152
#define SM_SQI  (6 * ASTG)      // 98304
#define SM_SQJ  (SM_SQI + 512)
#define SM_RED  (SM_SQI + 1024)
#define SMEM_BYTES (SM_SQI + 2048)   // 100352 -> 2 CTAs/SM

__device__ __half g_convA[NTOT * DDIM];  // A-fragment order, 4 MB
__device__ __half g_convB[NTOT * DDIM];  // B-fragment order, 4 MB
__device__ float  g_sq[NTOT];
__device__ float  g_colsum[DDIM];
__device__ double g_ssum;
__device__ double g_acc;
__device__ float  g_c4;

// ---------------------------------------------------------------------------
__device__ __forceinline__ float ex2f(float x) {
    float r; asm("ex2.approx.ftz.f32 %0, %1;" : "=f"(r) : "f"(x)); return r;
}
__device__ __forceinline__ uint32_t smem_u32(const void* p) {
    uint32_t a;
    asm("{ .reg .u64 t; cvta.to.shared.u64 t, %1; cvt.u32.u64 %0, t; }"
        : "=r"(a) : "l"(p));
    return a;
}
__device__ __forceinline__ void cp16(uint32_t dst, const void* src) {
    asm volatile("cp.async.cg.shared.global [%0], [%1], 16;"
                 :: "r"(dst), "l"(src));
}
__device__ __forceinline__ void cp_commit() {
    asm volatile("cp.async.commit_group;" ::: "memory");
}
template <int N>
__device__ __forceinline__ void cp_wait() {
    asm volatile("cp.async.wait_group %0;" :: "n"(N) : "memory");
}
__device__ __forceinline__ void mma_f16(float c[4], const uint4 a,
                                        const uint2 b) {
    asm volatile(
        "mma.sync.aligned.m16n8k16.row.col.f32.f16.f16.f32 "
        "{%0,%1,%2,%3},{%4,%5,%6,%7},{%8,%9},{%0,%1,%2,%3};"
        : "+f"(c[0]), "+f"(c[1]), "+f"(c[2]), "+f"(c[3])
        : "r"(a.x), "r"(a.y), "r"(a.z), "r"(a.w), "r"(b.x), "r"(b.y));
}
__device__ __forceinline__ const float* srow(const float* __restrict__ src,
                                             const float* __restrict__ tgt,
                                             int row) {
    return (row < NS) ? (src + (size_t)row * DDIM)
                      : (tgt + (size_t)(row - NS) * DDIM);
}
__device__ __forceinline__ uint32_t pack_h2(float lo, float hi) {
    __half2 h = __floats2half2_rn(lo, hi);
    return *(uint32_t*)&h;
}

// ---------------------------------------------------------------------------
__global__ void init_kernel() {
    int t = threadIdx.x;
    if (t < DDIM) g_colsum[t] = 0.0f;
    if (t == 0) { g_acc = 0.0; g_ssum = 0.0; }
}

// prep: sumsq per row + colsums (reads raw fp32 src/tgt).
__global__ void prep_kernel(const float* __restrict__ src,
                            const float* __restrict__ tgt) {
    const int tid  = threadIdx.x;
    const int w    = tid >> 5;
    const int lane = tid & 31;
    const int b    = blockIdx.x;
    const float* base = (b < 128) ? (src + (size_t)b * 32 * DDIM)
                                  : (tgt + (size_t)(b - 128) * 32 * DDIM);
    __shared__ float wsum[8];

    float mysq = 0.0f;
    #pragma unroll
    for (int it = 0; it < 4; it++) {
        int r = it * 8 + w;
        const float* p = base + (size_t)r * DDIM;
        float4 a = *(const float4*)(p + lane * 8);
        float4 c = *(const float4*)(p + lane * 8 + 4);
        float s = a.x*a.x + a.y*a.y + a.z*a.z + a.w*a.w
                + c.x*c.x + c.y*c.y + c.z*c.z + c.w*c.w;
        #pragma unroll
        for (int o = 16; o > 0; o >>= 1) s += __shfl_xor_sync(0xFFFFFFFFu, s, o);
        if (lane == 0) { g_sq[b * 32 + r] = s; mysq += s; }
    }
    if (lane == 0) wsum[w] = mysq;

    float cs = 0.0f;
    #pragma unroll 8
    for (int r = 0; r < 32; r++) cs += base[(size_t)r * DDIM + tid];
    atomicAdd(&g_colsum[tid], cs);

    __syncthreads();
    if (tid == 0) {
        float tot = 0.0f;
        #pragma unroll
        for (int i = 0; i < 8; i++) tot += wsum[i];
        atomicAdd(&g_ssum, (double)tot);
    }
}

// permute: build fp16 fragment-ordered copies.
// A: 262144 16B units (blocks [0,1024)): unit (RB, KS, lane) holds
//    {a0..a3} = half2 pairs for rows RB*16+g(,+8), k = KS*16+2*t4 (,+1,+8,+9).
// B: 524288 8B units (blocks [1024,3072)): unit (CB, KS, lane) holds
//    {b0,b1} for col CB*8+g, k = KS*16+2*t4 (,+1,+8,+9).
__global__ void permute_kernel(const float* __restrict__ src,
                               const float* __restrict__ tgt) {
    if (blockIdx.x < 1024) {
        int o    = blockIdx.x * 256 + threadIdx.x;  // 16B unit index
        int RB   = o >> 9;
        int rem  = o & 511;
        int KS   = rem >> 5;
        int lane = rem & 31;
        int g    = lane >> 2;
        int t4   = lane & 3;
        int r    = RB * 16 + g;
        int k    = KS * 16 + t4 * 2;
        const float* p0 = srow(src, tgt, r);
        const float* p1 = srow(src, tgt, r + 8);
        uint4 v;
        v.x = pack_h2(p0[k],     p0[k + 1]);
        v.y = pack_h2(p1[k],     p1[k + 1]);
        v.z = pack_h2(p0[k + 8], p0[k + 9]);
        v.w = pack_h2(p1[k + 8], p1[k + 9]);
        *(uint4*)((char*)g_convA + (size_t)o * 16) = v;
    } else {
        int o    = (blockIdx.x - 1024) * 256 + threadIdx.x;  // 8B unit index
        int CB   = o >> 9;
        int rem  = o & 511;
        int KS   = rem >> 5;
        int lane = rem & 31;
        int g    = lane >> 2;
        int t4   = lane & 3;
        int c    = CB * 8 + g;
        int k    = KS * 16 + t4 * 2;
        const float* p = srow(src, tgt, c);
        uint2 v;
        v.x = pack_h2(p[k],     p[k + 1]);
        v.y = pack_h2(p[k + 8], p[k + 9]);
        *(uint2*)((char*)g_convB + (size_t)o * 8) = v;
    }
}

__global__ void finalize_kernel() {
    const int t    = threadIdx.x;
    const int w    = t >> 5;
    const int lane = t & 31;
    __shared__ double wred[8];

    float c = g_colsum[t];
    double v = (double)c * (double)c;
    #pragma unroll
    for (int o = 16; o > 0; o >>= 1)
        v += __shfl_xor_sync(0xFFFFFFFFu, v, o);
    if (lane == 0) wred[w] = v;
    __syncthreads();
    if (t == 0) {
        double V = 0.0;
        #pragma unroll
        for (int i = 0; i < 8; i++) V += wred[i];
        double S      = g_ssum;
        double n      = (double)NTOT;
        double sum_l2 = 2.0 * n * S - 2.0 * V;
        double bw     = sum_l2 / (n * n - n);
        bw /= 4.0;                                   // KERNEL_MUL^(NUM//2)
        g_c4 = (float)(1.4426950408889634 / (bw * 16.0));
    }
}

// ---------------------------------------------------------------------------
// Fused tile kernel: 128x128 tile, fp16 fragment smem, 3-stage cp.async.
// Triangular grid: block idx -> (ti, tj) with ti <= tj.
__global__ void __launch_bounds__(256, 2)
mmd_kernel() {
    // triangular decode
    int idx = blockIdx.x;
    int ti = (int)((129.0 - sqrt(129.0 * 129.0 - 8.0 * (double)idx)) * 0.5);
    if (ti > NTILES - 1) ti = NTILES - 1;
    while (ti > 0 && idx < ti * NTILES - ti * (ti - 1) / 2) ti--;
    while (idx >= (ti + 1) * NTILES - (ti + 1) * ti / 2) ti++;
    const int tj = ti + (idx - (ti * NTILES - ti * (ti - 1) / 2));

    extern __shared__ char smem[];
    const uint32_t sbase = smem_u32(smem);
    float* sqi = (float*)(smem + SM_SQI);
    float* sqj = (float*)(smem + SM_SQJ);
    float* red = (float*)(smem + SM_RED);

    const int tid  = threadIdx.x;
    const int wid  = tid >> 5;
    const int lane = tid & 31;
    const int g    = lane >> 2;
    const int t4   = lane & 3;
    const int wm   = wid & 1;
    const int wn   = wid >> 1;

    const int i0 = ti * BM;
    const int j0 = tj * BM;
    const int Rb = ti * 8;      // A 16-row block base
    const int Cb = tj * 16;     // B 8-col block base

    if (tid < 128) sqi[tid]       = g_sq[i0 + tid];
    else           sqj[tid - 128] = g_sq[j0 + tid - 128];

    // cp.async coordinates: 4 x 16B per matrix per chunk per thread
    // A: ia -> rb = ia>>7, ks = (ia>>5)&3, lane = ia&31 ; dst = ia*16
    // B: ia -> cb = ia>>6, ks = (ia>>4)&3, slot = ia&15 ; dst = ia*16
    #pragma unroll
    for (int c = 0; c < 2; c++) {
        #pragma unroll
        for (int l = 0; l < 4; l++) {
            int ia = tid + l * 256;
            cp16(sbase + SM_A0 + c * ASTG + ia * 16,
                 (const char*)g_convA + (size_t)(Rb + (ia >> 7)) * 8192
                     + (c * 4 + ((ia >> 5) & 3)) * 512 + (ia & 31) * 16);
            cp16(sbase + SM_B0 + c * BSTG + ia * 16,
                 (const char*)g_convB + (size_t)(Cb + (ia >> 6)) * 4096
                     + (c * 4 + ((ia >> 4) & 3)) * 256 + (ia & 15) * 16);
        }
        cp_commit();
    }

    float acc[4][4][4];
    #pragma unroll
    for (int a = 0; a < 4; a++)
        #pragma unroll
        for (int b = 0; b < 4; b++)
            #pragma unroll
            for (int f = 0; f < 4; f++) acc[a][b][f] = 0.0f;

    int st_c = 0, st_p = 2;
    #pragma unroll 1
    for (int c = 0; c < NCHUNK; c++) {
        if (c + 2 < NCHUNK) {
            const int cc = c + 2;
            #pragma unroll
            for (int l = 0; l < 4; l++) {
                int ia = tid + l * 256;
                cp16(sbase + SM_A0 + st_p * ASTG + ia * 16,
                     (const char*)g_convA + (size_t)(Rb + (ia >> 7)) * 8192
                         + (cc * 4 + ((ia >> 5) & 3)) * 512 + (ia & 31) * 16);
                cp16(sbase + SM_B0 + st_p * BSTG + ia * 16,
                     (const char*)g_convB + (size_t)(Cb + (ia >> 6)) * 4096
                         + (cc * 4 + ((ia >> 4) & 3)) * 256 + (ia & 15) * 16);
            }
            cp_commit();
            cp_wait<2>();
        } else if (c + 1 < NCHUNK) {
            cp_wait<1>();
        } else {
            cp_wait<0>();
        }
        __syncthreads();

        const char* As = smem + SM_A0 + st_c * ASTG;
        const char* Bs = smem + SM_B0 + st_c * BSTG;

        #pragma unroll
        for (int s = 0; s < 4; s++) {            // 4 k-steps of K=16
            uint4 af[4];
            uint2 bf[4];
            #pragma unroll
            for (int ma = 0; ma < 4; ma++)
                af[ma] = *(const uint4*)(As + (wm * 4 + ma) * 2048 + s * 512
                                            + lane * 16);
            #pragma unroll
            for (int nb = 0; nb < 4; nb++)
                bf[nb] = *(const uint2*)(Bs + (wn * 4 + nb) * 1024 + s * 256
                                            + lane * 8);
            #pragma unroll
            for (int ma = 0; ma < 4; ma++)
                #pragma unroll
                for (int nb = 0; nb < 4; nb++)
                    mma_f16(acc[ma][nb], af[ma], bf[nb]);
        }
        __syncthreads();

        st_c = (st_c == 2) ? 0 : st_c + 1;
        st_p = (st_p == 2) ? 0 : st_p + 1;
    }

    // --- epilogue ---
    const float c4 = g_c4;
    float si[4][2], sj[4][2];
    #pragma unroll
    for (int ma = 0; ma < 4; ma++) {
        si[ma][0] = sqi[wm * 64 + ma * 16 + g];
        si[ma][1] = sqi[wm * 64 + ma * 16 + g + 8];
    }
    #pragma unroll
    for (int nb = 0; nb < 4; nb++) {
        sj[nb][0] = sqj[wn * 32 + nb * 8 + 2 * t4];
        sj[nb][1] = sqj[wn * 32 + nb * 8 + 2 * t4 + 1];
    }

    float part = 0.0f;
    #pragma unroll
    for (int ma = 0; ma < 4; ma++) {
        #pragma unroll
        for (int nb = 0; nb < 4; nb++) {
            #pragma unroll
            for (int f = 0; f < 4; f++) {
                float nl2 = 2.0f * acc[ma][nb][f] - si[ma][f >> 1] - sj[nb][f & 1];
                float u   = ex2f(nl2 * c4);
                float u2  = u  * u;
                float u4  = u2 * u2;
                float u8  = u4 * u4;
                float u16 = u8 * u8;
                part += (u + u2) + (u4 + u8) + u16;
            }
        }
    }

    float w  = (ti == tj) ? 1.0f : 2.0f;
    float sg = ((ti < NTILES / 2) == (tj < NTILES / 2)) ? 1.0f : -1.0f;
    part *= w * sg;

    red[tid] = part;
    __syncthreads();
    #pragma unroll
    for (int s = 128; s > 0; s >>= 1) {
        if (tid < s) red[tid] += red[tid + s];
        __syncthreads();
    }
    if (tid == 0) atomicAdd(&g_acc, (double)red[0]);
}

__global__ void writeout_kernel(float* __restrict__ out) {
    out[0] = (float)(g_acc / ((double)NS * (double)NS));
}

// ---------------------------------------------------------------------------
extern "C" void kernel_launch(void* const* d_in, const int* in_sizes, int n_in,
                              void* d_out, int out_size) {
    const float* src = (const float*)d_in[0];
    const float* tgt = (const float*)d_in[1];
    float* out = (float*)d_out;

    cudaFuncSetAttribute(mmd_kernel,
                         cudaFuncAttributeMaxDynamicSharedMemorySize, SMEM_BYTES);

    init_kernel<<<1, 256>>>();
    prep_kernel<<<256, 256>>>(src, tgt);
    permute_kernel<<<3072, 256>>>(src, tgt);
    finalize_kernel<<<1, 256>>>();
    mmd_kernel<<<NBLK, 256, SMEM_BYTES>>>();
    writeout_kernel<<<1, 1>>>(out);
}